// round 1
// baseline (speedup 1.0000x reference)
#include <cuda_runtime.h>
#include <cuda_bf16.h>
#include <cstdint>

// LSTM: B=4096, T=2048, I=1, H=8, then FC [H]->[4].
// Decomposition: 8 lanes per batch (lane = hidden unit), 4 batches per warp.
// Per step: gates via shfl-broadcast h (8 shfl shared across 4 gate FMAs each),
// pointwise cell update fully lane-local. Activations via EX2+RCP with the
// log2e prescale folded into the (register-resident) weights.

#define B_TOTAL 4096
#define T_STEPS 2048
#define LOG2E_F 1.4426950408889634f

__device__ __forceinline__ float ex2f(float x) {
    float r; asm("ex2.approx.f32 %0, %1;" : "=f"(r) : "f"(x)); return r;
}
__device__ __forceinline__ float rcpf(float x) {
    float r; asm("rcp.approx.f32 %0, %1;" : "=f"(r) : "f"(x)); return r;
}

__global__ __launch_bounds__(32, 32)
void lstm_fused_kernel(const float* __restrict__ x,
                       const float* __restrict__ w_ih,
                       const float* __restrict__ w_hh,
                       const float* __restrict__ b_ih,
                       const float* __restrict__ b_hh,
                       const float* __restrict__ w_fc,
                       const float* __restrict__ b_fc,
                       float* __restrict__ out)
{
    const int tid = blockIdx.x * blockDim.x + threadIdx.x;
    const int b   = tid >> 3;   // batch index (one per 8-lane group)
    const int u   = tid & 7;    // hidden unit owned by this lane

    // Gate rows in PyTorch order: i=[0,8), f=[8,16), g=[16,24), o=[24,32).
    // Prescale so that:
    //   sigmoid(z) = 1 / (1 + exp2(-z*log2e))       -> scale rows i,f,o by -log2e
    //   tanh(z)    = 2 / (1 + exp2(-2z*log2e)) - 1  -> scale row  g   by -2*log2e
    float wh[4][8];  // w_hh rows for (i,f,g,o) of unit u, prescaled
    float wx[4];     // w_ih (I=1) contributions, prescaled
    float bb[4];     // b_ih + b_hh, prescaled
    {
        const float scale[4] = { -LOG2E_F, -LOG2E_F, -2.0f * LOG2E_F, -LOG2E_F };
#pragma unroll
        for (int t = 0; t < 4; t++) {
            const int row = t * 8 + u;
            const float s = scale[t];
            wx[t] = s * w_ih[row];
            bb[t] = s * (b_ih[row] + b_hh[row]);
#pragma unroll
            for (int j = 0; j < 8; j++)
                wh[t][j] = s * w_hh[row * 8 + j];
        }
    }

    float h = 0.0f, c = 0.0f;

    const float4* xb = reinterpret_cast<const float4*>(x + (size_t)b * T_STEPS);

    // Software prefetch of x (one float4 = 4 timesteps ahead).
    float4 xv = xb[0];

    for (int t4 = 0; t4 < T_STEPS / 4; t4++) {
        float4 xnext;
        if (t4 + 1 < T_STEPS / 4) xnext = xb[t4 + 1];

        const float xs[4] = { xv.x, xv.y, xv.z, xv.w };
#pragma unroll
        for (int k = 0; k < 4; k++) {
            const float xt = xs[k];
            float a0 = fmaf(xt, wx[0], bb[0]);   // i pre-act (prescaled)
            float a1 = fmaf(xt, wx[1], bb[1]);   // f
            float a2 = fmaf(xt, wx[2], bb[2]);   // g
            float a3 = fmaf(xt, wx[3], bb[3]);   // o
#pragma unroll
            for (int j = 0; j < 8; j++) {
                const float hj = __shfl_sync(0xffffffffu, h, j, 8);
                a0 = fmaf(hj, wh[0][j], a0);
                a1 = fmaf(hj, wh[1][j], a1);
                a2 = fmaf(hj, wh[2][j], a2);
                a3 = fmaf(hj, wh[3][j], a3);
            }
            // sigmoid(z) = rcp(1 + exp2(a)),  tanh(z) = 2*rcp(1 + exp2(a)) - 1
            const float ri = rcpf(1.0f + ex2f(a0));        // i
            const float rf = rcpf(1.0f + ex2f(a1));        // f
            const float rg = rcpf(1.0f + ex2f(a2));        // -> tanh(g)
            const float ro = rcpf(1.0f + ex2f(a3));        // o
            const float tg = fmaf(2.0f, rg, -1.0f);

            c = fmaf(rf, c, ri * tg);

            const float rc = rcpf(1.0f + ex2f(-2.0f * LOG2E_F * c));
            const float tc = fmaf(2.0f, rc, -1.0f);
            h = ro * tc;
        }
        xv = xnext;
    }

    // FC head: out[b][k] = b_fc[k] + sum_u h_u * w_fc[k*8 + u]
    float p0 = h * w_fc[0 * 8 + u];
    float p1 = h * w_fc[1 * 8 + u];
    float p2 = h * w_fc[2 * 8 + u];
    float p3 = h * w_fc[3 * 8 + u];
#pragma unroll
    for (int off = 4; off >= 1; off >>= 1) {
        p0 += __shfl_xor_sync(0xffffffffu, p0, off, 8);
        p1 += __shfl_xor_sync(0xffffffffu, p1, off, 8);
        p2 += __shfl_xor_sync(0xffffffffu, p2, off, 8);
        p3 += __shfl_xor_sync(0xffffffffu, p3, off, 8);
    }
    if (u < 4) {
        const float pk = (u == 0) ? p0 : (u == 1) ? p1 : (u == 2) ? p2 : p3;
        out[b * 4 + u] = pk + b_fc[u];
    }
}

extern "C" void kernel_launch(void* const* d_in, const int* in_sizes, int n_in,
                              void* d_out, int out_size)
{
    const float* x    = (const float*)d_in[0];
    const float* w_ih = (const float*)d_in[1];
    const float* w_hh = (const float*)d_in[2];
    const float* b_ih = (const float*)d_in[3];
    const float* b_hh = (const float*)d_in[4];
    const float* w_fc = (const float*)d_in[5];
    const float* b_fc = (const float*)d_in[6];
    float* out = (float*)d_out;

    // 8 lanes per batch -> 4096*8 = 32768 threads. 32-thread blocks (1024
    // blocks) minimize wave-quantization imbalance across 148 SMs.
    const int threads = 32;
    const int blocks  = (B_TOTAL * 8) / threads;
    lstm_fused_kernel<<<blocks, threads>>>(x, w_ih, w_hh, b_ih, b_hh, w_fc, b_fc, out);
}

// round 2
// speedup vs baseline: 1.0916x; 1.0916x over previous
#include <cuda_runtime.h>
#include <cuda_bf16.h>
#include <cstdint>

// LSTM: B=4096, T=2048, I=1, H=8, then FC [H]->[4].
// Decomposition (R2): 16 lanes per batch -> 2048 warps (2x R1) to hide the
// serial recurrence latency. Lane l=u (0..7) owns gates (i,g) of unit u;
// lane l=8+u owns (f,o). Both halves redundantly maintain (c,h), so the
// h-broadcast is a width-8 shfl and the gate exchange is 2 xor-8 shfls of
// activated values. Activations exact via ex2+rcp with log2e prescale folded
// into register-resident weights.

#define B_TOTAL 4096
#define T_STEPS 2048
#define LOG2E_F 1.4426950408889634f

__device__ __forceinline__ float ex2f(float x) {
    float r; asm("ex2.approx.f32 %0, %1;" : "=f"(r) : "f"(x)); return r;
}
__device__ __forceinline__ float rcpf(float x) {
    float r; asm("rcp.approx.f32 %0, %1;" : "=f"(r) : "f"(x)); return r;
}

__global__ __launch_bounds__(32, 16)
void lstm_fused_kernel(const float* __restrict__ x,
                       const float* __restrict__ w_ih,
                       const float* __restrict__ w_hh,
                       const float* __restrict__ b_ih,
                       const float* __restrict__ b_hh,
                       const float* __restrict__ w_fc,
                       const float* __restrict__ b_fc,
                       float* __restrict__ out)
{
    const int tid = blockIdx.x * blockDim.x + threadIdx.x;
    const int b   = tid >> 4;          // batch index (16 lanes per batch)
    const int l   = tid & 15;          // lane within batch group
    const int u   = l & 7;             // hidden unit owned by this lane
    const bool hi = (l >= 8);          // upper half: gates (f,o); lower: (i,g)

    // PyTorch gate rows: i=[0,8), f=[8,16), g=[16,24), o=[24,32).
    // Gate A: lower->i (sigmoid), upper->f (sigmoid).
    // Gate B: lower->g (tanh),    upper->o (sigmoid).
    // Prescale: sigmoid(z) = rcp(1 + exp2(-z*log2e))        -> s = -log2e
    //           tanh(z)    = 2*rcp(1 + exp2(-2z*log2e)) - 1 -> s = -2*log2e
    const int   rowA = hi ? (8 + u)  : u;
    const int   rowB = hi ? (24 + u) : (16 + u);
    const float sA   = -LOG2E_F;
    const float sB   = hi ? -LOG2E_F : (-2.0f * LOG2E_F);
    const float alB  = hi ? 1.0f : 2.0f;   // gateB = alB * r + beB
    const float beB  = hi ? 0.0f : -1.0f;

    float whA[8], whB[8];
    float wxA, wxB, bbA, bbB;
    {
        wxA = sA * w_ih[rowA];
        wxB = sB * w_ih[rowB];
        bbA = sA * (b_ih[rowA] + b_hh[rowA]);
        bbB = sB * (b_ih[rowB] + b_hh[rowB]);
#pragma unroll
        for (int j = 0; j < 8; j++) {
            whA[j] = sA * w_hh[rowA * 8 + j];
            whB[j] = sB * w_hh[rowB * 8 + j];
        }
    }

    float h = 0.0f, c = 0.0f;

    const float4* xb = reinterpret_cast<const float4*>(x + (size_t)b * T_STEPS);
    float4 xv = xb[0];

    for (int t4 = 0; t4 < T_STEPS / 4; t4++) {
        float4 xnext;
        if (t4 + 1 < T_STEPS / 4) xnext = xb[t4 + 1];

        const float xs[4] = { xv.x, xv.y, xv.z, xv.w };
#pragma unroll
        for (int k = 0; k < 4; k++) {
            const float xt = xs[k];
            float aA = fmaf(xt, wxA, bbA);
            float aB = fmaf(xt, wxB, bbB);
#pragma unroll
            for (int j = 0; j < 8; j++) {
                const float hj = __shfl_sync(0xffffffffu, h, j, 8);
                aA = fmaf(hj, whA[j], aA);
                aB = fmaf(hj, whB[j], aB);
            }
            // gateA: sigmoid (both halves). gateB: tanh (lower) / sigmoid (upper).
            const float rA = rcpf(1.0f + ex2f(aA));
            const float rB = rcpf(1.0f + ex2f(aB));
            const float gB = fmaf(alB, rB, beB);

            // Exchange activated gates across halves (xor 8 within the 16-group).
            const float oA = __shfl_xor_sync(0xffffffffu, rA, 8, 16);
            const float oB = __shfl_xor_sync(0xffffffffu, gB, 8, 16);

            // lower: (i,g) own, (f,o) other.  upper: (f,o) own, (i,g) other.
            const float iv = hi ? oA : rA;
            const float fv = hi ? rA : oA;
            const float gv = hi ? oB : gB;
            const float ov = hi ? gB : oB;

            c = fmaf(fv, c, iv * gv);

            const float rc = rcpf(1.0f + ex2f(-2.0f * LOG2E_F * c));
            const float tc = fmaf(2.0f, rc, -1.0f);
            h = ov * tc;
        }
        xv = xnext;
    }

    // FC head: out[b][k] = b_fc[k] + sum_u h_u * w_fc[k*8 + u]
    // h_u is present in lane u (and redundantly in lane 8+u); reduce width 8.
    float p0 = h * w_fc[0 * 8 + u];
    float p1 = h * w_fc[1 * 8 + u];
    float p2 = h * w_fc[2 * 8 + u];
    float p3 = h * w_fc[3 * 8 + u];
#pragma unroll
    for (int off = 4; off >= 1; off >>= 1) {
        p0 += __shfl_xor_sync(0xffffffffu, p0, off, 8);
        p1 += __shfl_xor_sync(0xffffffffu, p1, off, 8);
        p2 += __shfl_xor_sync(0xffffffffu, p2, off, 8);
        p3 += __shfl_xor_sync(0xffffffffu, p3, off, 8);
    }
    if (l < 4) {
        const float pk = (l == 0) ? p0 : (l == 1) ? p1 : (l == 2) ? p2 : p3;
        out[b * 4 + l] = pk + b_fc[l];
    }
}

extern "C" void kernel_launch(void* const* d_in, const int* in_sizes, int n_in,
                              void* d_out, int out_size)
{
    const float* x    = (const float*)d_in[0];
    const float* w_ih = (const float*)d_in[1];
    const float* w_hh = (const float*)d_in[2];
    const float* b_ih = (const float*)d_in[3];
    const float* b_hh = (const float*)d_in[4];
    const float* w_fc = (const float*)d_in[5];
    const float* b_fc = (const float*)d_in[6];
    float* out = (float*)d_out;

    // 16 lanes per batch -> 4096*16 = 65536 threads = 2048 warps.
    const int threads = 32;
    const int blocks  = (B_TOTAL * 16) / threads;
    lstm_fused_kernel<<<blocks, threads>>>(x, w_ih, w_hh, b_ih, b_hh, w_fc, b_fc, out);
}

// round 3
// speedup vs baseline: 1.7474x; 1.6008x over previous
#include <cuda_runtime.h>
#include <cuda_bf16.h>
#include <cstdint>

// LSTM: B=4096, T=2048, I=1, H=8, then FC [H]->[4].
// R3: 16 lanes/batch (2048 warps). Lower 8 lanes of each 16-group own unit u's
// gates (i,g) AND the (c,h) state; upper 8 lanes compute gates (f,o) only.
// All activations via MUFU.TANH (sigmoid(z) = 0.5*tanh(z/2)+0.5, 0.5 prescale
// folded into weights). Gate exchange: 2 xor-8 shfls; upper half's received
// values are never consumed (no selects). h-broadcast: width-16 shfl reading
// lanes 0-7, so only the lower half needs valid h.

#define B_TOTAL 4096
#define T_STEPS 2048

__device__ __forceinline__ float tanhf_mufu(float x) {
    float r; asm("tanh.approx.f32 %0, %1;" : "=f"(r) : "f"(x)); return r;
}

__global__ __launch_bounds__(32, 16)
void lstm_fused_kernel(const float* __restrict__ x,
                       const float* __restrict__ w_ih,
                       const float* __restrict__ w_hh,
                       const float* __restrict__ b_ih,
                       const float* __restrict__ b_hh,
                       const float* __restrict__ w_fc,
                       const float* __restrict__ b_fc,
                       float* __restrict__ out)
{
    const int tid = blockIdx.x * blockDim.x + threadIdx.x;
    const int b   = tid >> 4;          // batch index (16 lanes per batch)
    const int l   = tid & 15;          // lane within batch group
    const int u   = l & 7;             // hidden unit owned by this lane
    const bool hi = (l >= 8);          // upper half: gates (f,o); lower: (i,g)

    // PyTorch gate rows: i=[0,8), f=[8,16), g=[16,24), o=[24,32).
    // Gate A: lower->i (sigmoid), upper->f (sigmoid):  rA = 0.5*tanh(0.5*a)+0.5
    //   -> prescale 0.5 into row, post fma(0.5, t, 0.5)
    // Gate B: lower->g (tanh): gB = tanh(a)            (sB=1,   alB=1,   beB=0)
    //         upper->o (sigmoid): gB = 0.5*tanh(.5a)+.5 (sB=0.5, alB=0.5, beB=0.5)
    const int   rowA = hi ? (8 + u)  : u;
    const int   rowB = hi ? (24 + u) : (16 + u);
    const float sA   = 0.5f;
    const float sB   = hi ? 0.5f : 1.0f;
    const float alB  = hi ? 0.5f : 1.0f;
    const float beB  = hi ? 0.5f : 0.0f;

    float whA[8], whB[8];
    float wxA, wxB, bbA, bbB;
    {
        wxA = sA * w_ih[rowA];
        wxB = sB * w_ih[rowB];
        bbA = sA * (b_ih[rowA] + b_hh[rowA]);
        bbB = sB * (b_ih[rowB] + b_hh[rowB]);
#pragma unroll
        for (int j = 0; j < 8; j++) {
            whA[j] = sA * w_hh[rowA * 8 + j];
            whB[j] = sB * w_hh[rowB * 8 + j];
        }
    }

    float h = 0.0f, c = 0.0f;   // valid in lower half only

    const float4* xb = reinterpret_cast<const float4*>(x + (size_t)b * T_STEPS);
    float4 xv = xb[0];

    for (int t4 = 0; t4 < T_STEPS / 4; t4++) {
        float4 xnext;
        if (t4 + 1 < T_STEPS / 4) xnext = xb[t4 + 1];

        const float xs[4] = { xv.x, xv.y, xv.z, xv.w };
#pragma unroll
        for (int k = 0; k < 4; k++) {
            const float xt = xs[k];
            float aA = fmaf(xt, wxA, bbA);
            float aB = fmaf(xt, wxB, bbB);
#pragma unroll
            for (int j = 0; j < 8; j++) {
                // width 16, src j<8: reads lane j of the 16-group (lower half h)
                const float hj = __shfl_sync(0xffffffffu, h, j, 16);
                aA = fmaf(hj, whA[j], aA);
                aB = fmaf(hj, whB[j], aB);
            }
            const float tA = tanhf_mufu(aA);
            const float tB = tanhf_mufu(aB);
            const float rA = fmaf(0.5f, tA, 0.5f);   // sigmoid: i (lo) / f (hi)
            const float gB = fmaf(alB,  tB, beB);    // tanh g (lo) / sigmoid o (hi)

            // lower: m = i*g.  (upper computes garbage; never consumed)
            const float m  = rA * gB;
            // xor-8 exchange within 16-group: lower receives upper's values.
            const float f_r = __shfl_xor_sync(0xffffffffu, rA, 8, 16); // lo gets f
            const float o_r = __shfl_xor_sync(0xffffffffu, gB, 8, 16); // lo gets o

            c = fmaf(f_r, c, m);            // valid in lower half
            const float tc = tanhf_mufu(c);
            h = o_r * tc;                    // valid in lower half
        }
        xv = xnext;
    }

    // FC head: out[b][k] = b_fc[k] + sum_u h_u * w_fc[k*8 + u]
    // h valid in lanes 0-7 of the 16-group; width-8 reduction keeps segments
    // separate, so the lower segment's result is correct.
    float p0 = h * w_fc[0 * 8 + u];
    float p1 = h * w_fc[1 * 8 + u];
    float p2 = h * w_fc[2 * 8 + u];
    float p3 = h * w_fc[3 * 8 + u];
#pragma unroll
    for (int off = 4; off >= 1; off >>= 1) {
        p0 += __shfl_xor_sync(0xffffffffu, p0, off, 8);
        p1 += __shfl_xor_sync(0xffffffffu, p1, off, 8);
        p2 += __shfl_xor_sync(0xffffffffu, p2, off, 8);
        p3 += __shfl_xor_sync(0xffffffffu, p3, off, 8);
    }
    if (l < 4) {
        const float pk = (l == 0) ? p0 : (l == 1) ? p1 : (l == 2) ? p2 : p3;
        out[b * 4 + l] = pk + b_fc[l];
    }
}

extern "C" void kernel_launch(void* const* d_in, const int* in_sizes, int n_in,
                              void* d_out, int out_size)
{
    const float* x    = (const float*)d_in[0];
    const float* w_ih = (const float*)d_in[1];
    const float* w_hh = (const float*)d_in[2];
    const float* b_ih = (const float*)d_in[3];
    const float* b_hh = (const float*)d_in[4];
    const float* w_fc = (const float*)d_in[5];
    const float* b_fc = (const float*)d_in[6];
    float* out = (float*)d_out;

    const int threads = 32;
    const int blocks  = (B_TOTAL * 16) / threads;   // 2048 blocks
    lstm_fused_kernel<<<blocks, threads>>>(x, w_ih, w_hh, b_ih, b_hh, w_fc, b_fc, out);
}